// round 5
// baseline (speedup 1.0000x reference)
#include <cuda_runtime.h>
#include <cuda_bf16.h>

// ---------------------------------------------------------------------------
// Problem constants
// ---------------------------------------------------------------------------
#define NTOK   16384           // B*T = 8*2048
#define DMODEL 1024
#define DQ     256
#define DH     512
#define NHEADS 8               // [sign | dig0..dig5 | aux]
#define W1COLS 4096            // 8*512
#define OUT_SIGN 0
#define OUT_DIG  49152         // NTOK*3
#define OUT_AUX  1032192       // NTOK*3 + NTOK*60

// ---------------------------------------------------------------------------
// Device scratch (no allocation allowed)
// ---------------------------------------------------------------------------
__device__ float g_h[(long)NTOK * W1COLS];     // 256 MB: GEMM1 pre (first 64MB) then GEMM2 out
__device__ float g_ctx[(long)NTOK * DMODEL];   // 64 MB: context after LN+GELU
__device__ float g_W1all[DMODEL * W1COLS];     // 16 MB: packed second-layer weights
__device__ float g_opw[9 * DMODEL];            // op_embed @ ctx_w[1024:1280]
__device__ float g_ptw[10 * DMODEL];           // pt_embed @ ctx_w[1280:1536]
__device__ float g_posh[6 * DH];               // pos_embed[p] @ dig_w1[p,1024:,:] + dig_b1[p]

// ---------------------------------------------------------------------------
// Helpers
// ---------------------------------------------------------------------------
__device__ __forceinline__ unsigned f2tf(float x) {
    unsigned r;
    asm("cvt.rna.tf32.f32 %0, %1;" : "=r"(r) : "f"(x));
    return r;
}

__device__ __forceinline__ void mma_tf32(float* c, const unsigned* a, const unsigned* b) {
    asm volatile(
        "mma.sync.aligned.m16n8k8.row.col.f32.tf32.tf32.f32 "
        "{%0,%1,%2,%3},{%4,%5,%6,%7},{%8,%9},{%0,%1,%2,%3};"
        : "+f"(c[0]), "+f"(c[1]), "+f"(c[2]), "+f"(c[3])
        : "r"(a[0]), "r"(a[1]), "r"(a[2]), "r"(a[3]), "r"(b[0]), "r"(b[1]));
}

__device__ __forceinline__ float wred(float v) {
#pragma unroll
    for (int o = 16; o; o >>= 1) v += __shfl_xor_sync(0xFFFFFFFFu, v, o);
    return v;
}

__device__ __forceinline__ float gelu_exact(float x) {
    return 0.5f * x * (1.0f + erff(x * 0.7071067811865475f));
}

// ---------------------------------------------------------------------------
// Prep: small GEMMs folding embeddings into additive tables. 88 blocks x 256.
//   blocks [0,36):  g_opw   (9 rows x 4 col-chunks)
//   blocks [36,76): g_ptw   (10 rows x 4 col-chunks)
//   blocks [76,88): g_posh  (6 positions x 2 col-chunks), includes dig_b1
// ---------------------------------------------------------------------------
__global__ void prep_small(const float* __restrict__ op_embed,
                           const float* __restrict__ pt_embed,
                           const float* __restrict__ pos_embed,
                           const float* __restrict__ ctx_w,
                           const float* __restrict__ dig_w1,
                           const float* __restrict__ dig_b1) {
    __shared__ float e[256];
    int bid = blockIdx.x, tid = threadIdx.x;
    if (bid < 36) {
        int r = bid >> 2, j = (bid & 3) * 256 + tid;
        e[tid] = op_embed[r * 256 + tid];
        __syncthreads();
        float acc = 0.f;
#pragma unroll 8
        for (int q = 0; q < 256; q++)
            acc += e[q] * ctx_w[(1024 + q) * 1024 + j];
        g_opw[r * 1024 + j] = acc;
    } else if (bid < 76) {
        int idx = bid - 36;
        int r = idx >> 2, j = (idx & 3) * 256 + tid;
        e[tid] = pt_embed[r * 256 + tid];
        __syncthreads();
        float acc = 0.f;
#pragma unroll 8
        for (int q = 0; q < 256; q++)
            acc += e[q] * ctx_w[(1280 + q) * 1024 + j];
        g_ptw[r * 1024 + j] = acc;
    } else {
        int idx = bid - 76;
        int p = idx >> 1, c = (idx & 1) * 256 + tid;
        e[tid] = pos_embed[p * 256 + tid];
        __syncthreads();
        float acc = dig_b1[p * 512 + c];
        const float* w = dig_w1 + (long)p * 655360 + 1024L * 512 + c;
#pragma unroll 8
        for (int q = 0; q < 256; q++)
            acc += e[q] * w[q * 512];
        g_posh[p * 512 + c] = acc;
    }
}

// ---------------------------------------------------------------------------
// Pack W1all[k][j]: j -> head h = j>>9, col c = j&511.
// ---------------------------------------------------------------------------
__global__ void pack_w1(const float* __restrict__ sign_w1,
                        const float* __restrict__ dig_w1,
                        const float* __restrict__ aux_w1) {
    int idx = blockIdx.x * 256 + threadIdx.x;      // 0 .. 4194303
    int k = idx >> 12;
    int j = idx & 4095;
    int h = j >> 9;
    int c = j & 511;
    float w;
    if (h == 0)       w = sign_w1[k * 512 + c];
    else if (h < 7)   w = dig_w1[(long)(h - 1) * 655360 + (long)k * 512 + c];
    else              w = aux_w1[k * 512 + c];
    g_W1all[idx] = w;
}

// ---------------------------------------------------------------------------
// TF32 tensor-core GEMM: C[M,N] = A[M,K] @ B[K,N].
// BM=128, BN=128, BK=16, 256 threads (8 warps, 4x2), warp tile 32x64,
// 16 m16n8k8 mma per k8 step per warp. Padded smem -> conflict-free frag reads
// (As stride 20, Bs stride 136, both verified distinct banks per quad layout).
// ---------------------------------------------------------------------------
__device__ __forceinline__ void gemm_body(const float* __restrict__ A,
                                          const float* __restrict__ B,
                                          float* __restrict__ C,
                                          int K, int lda, int ldb, int ldc) {
    __shared__ unsigned As[128 * 20];
    __shared__ unsigned Bs[16 * 136];

    const int tid  = threadIdx.x;
    const int warp = tid >> 5, lane = tid & 31;
    const int wm = warp & 3, wn = warp >> 2;
    const int grp = lane >> 2, qk = lane & 3;

    const long bm = (long)blockIdx.y * 128;
    const long bn = (long)blockIdx.x * 128;

    const float* Abase = A + bm * lda;
    const float* Bbase = B + bn;

    const int arow0 = tid >> 2, ac4 = (tid & 3) * 4;   // A: rows arow0, arow0+64
    const int brow0 = tid >> 5, bc4 = (tid & 31) * 4;  // B: rows brow0, brow0+8

    float4 pa0, pa1, pb0, pb1;

    float c[2][8][4];
#pragma unroll
    for (int mi = 0; mi < 2; mi++)
#pragma unroll
        for (int ni = 0; ni < 8; ni++)
#pragma unroll
            for (int q = 0; q < 4; q++) c[mi][ni][q] = 0.f;

    // first tile
    pa0 = *(const float4*)(Abase + (long)arow0 * lda + ac4);
    pa1 = *(const float4*)(Abase + (long)(arow0 + 64) * lda + ac4);
    pb0 = *(const float4*)(Bbase + (long)brow0 * ldb + bc4);
    pb1 = *(const float4*)(Bbase + (long)(brow0 + 8) * ldb + bc4);
    {
        unsigned* p = &As[arow0 * 20 + ac4];
        p[0] = f2tf(pa0.x); p[1] = f2tf(pa0.y); p[2] = f2tf(pa0.z); p[3] = f2tf(pa0.w);
        unsigned* p2 = &As[(arow0 + 64) * 20 + ac4];
        p2[0] = f2tf(pa1.x); p2[1] = f2tf(pa1.y); p2[2] = f2tf(pa1.z); p2[3] = f2tf(pa1.w);
        unsigned* q = &Bs[brow0 * 136 + bc4];
        q[0] = f2tf(pb0.x); q[1] = f2tf(pb0.y); q[2] = f2tf(pb0.z); q[3] = f2tf(pb0.w);
        unsigned* q2 = &Bs[(brow0 + 8) * 136 + bc4];
        q2[0] = f2tf(pb1.x); q2[1] = f2tf(pb1.y); q2[2] = f2tf(pb1.z); q2[3] = f2tf(pb1.w);
    }
    __syncthreads();

    for (int k0 = 0; k0 < K; k0 += 16) {
        const bool more = (k0 + 16) < K;
        if (more) {
            pa0 = *(const float4*)(Abase + (long)arow0 * lda + (k0 + 16) + ac4);
            pa1 = *(const float4*)(Abase + (long)(arow0 + 64) * lda + (k0 + 16) + ac4);
            pb0 = *(const float4*)(Bbase + (long)(k0 + 16 + brow0) * ldb + bc4);
            pb1 = *(const float4*)(Bbase + (long)(k0 + 16 + brow0 + 8) * ldb + bc4);
        }

#pragma unroll
        for (int kk = 0; kk < 16; kk += 8) {
            unsigned af[2][4], bf[8][2];
#pragma unroll
            for (int mi = 0; mi < 2; mi++) {
                int r = wm * 32 + mi * 16 + grp;
                af[mi][0] = As[r * 20 + kk + qk];
                af[mi][1] = As[(r + 8) * 20 + kk + qk];
                af[mi][2] = As[r * 20 + kk + qk + 4];
                af[mi][3] = As[(r + 8) * 20 + kk + qk + 4];
            }
#pragma unroll
            for (int ni = 0; ni < 8; ni++) {
                int col = wn * 64 + ni * 8 + grp;
                bf[ni][0] = Bs[(kk + qk) * 136 + col];
                bf[ni][1] = Bs[(kk + qk + 4) * 136 + col];
            }
#pragma unroll
            for (int mi = 0; mi < 2; mi++)
#pragma unroll
                for (int ni = 0; ni < 8; ni++)
                    mma_tf32(c[mi][ni], af[mi], bf[ni]);
        }

        __syncthreads();
        if (more) {
            unsigned* p = &As[arow0 * 20 + ac4];
            p[0] = f2tf(pa0.x); p[1] = f2tf(pa0.y); p[2] = f2tf(pa0.z); p[3] = f2tf(pa0.w);
            unsigned* p2 = &As[(arow0 + 64) * 20 + ac4];
            p2[0] = f2tf(pa1.x); p2[1] = f2tf(pa1.y); p2[2] = f2tf(pa1.z); p2[3] = f2tf(pa1.w);
            unsigned* q = &Bs[brow0 * 136 + bc4];
            q[0] = f2tf(pb0.x); q[1] = f2tf(pb0.y); q[2] = f2tf(pb0.z); q[3] = f2tf(pb0.w);
            unsigned* q2 = &Bs[(brow0 + 8) * 136 + bc4];
            q2[0] = f2tf(pb1.x); q2[1] = f2tf(pb1.y); q2[2] = f2tf(pb1.z); q2[3] = f2tf(pb1.w);
            __syncthreads();
        }
    }

    // epilogue: float2 stores (cols even -> 8B aligned)
#pragma unroll
    for (int mi = 0; mi < 2; mi++) {
#pragma unroll
        for (int ni = 0; ni < 8; ni++) {
            long r  = bm + wm * 32 + mi * 16 + grp;
            long cc = bn + wn * 64 + ni * 8 + qk * 2;
            float2 v0 = make_float2(c[mi][ni][0], c[mi][ni][1]);
            float2 v1 = make_float2(c[mi][ni][2], c[mi][ni][3]);
            *(float2*)(C + r * ldc + cc)        = v0;
            *(float2*)(C + (r + 8) * ldc + cc)  = v1;
        }
    }
}

__global__ __launch_bounds__(256) void gemm1_kernel(const float* __restrict__ A,
                                                    const float* __restrict__ B) {
    gemm_body(A, B, g_h, 1024, 1024, 1024, 1024);   // hidden @ ctx_w[:1024] -> g_h (pre)
}

__global__ __launch_bounds__(256) void gemm2_kernel() {
    gemm_body(g_ctx, g_W1all, g_h, 1024, 1024, 4096, 4096);
}

// ---------------------------------------------------------------------------
// Context epilogue: pre + opw[op_b] + ptw[pt_n] + ctx_b -> LN(1024) -> GELU.
// One block (256 thr) per token; 4 elems/thread via float4.
// ---------------------------------------------------------------------------
__global__ __launch_bounds__(256) void ln_ctx_kernel(const int* __restrict__ op_t,
                                                     const int* __restrict__ pt_t,
                                                     const float* __restrict__ ctx_b,
                                                     const float* __restrict__ ctx_g,
                                                     const float* __restrict__ ctx_beta) {
    __shared__ float red[8];
    const int n = blockIdx.x;
    const int tid = threadIdx.x;
    const int warp = tid >> 5, lane = tid & 31;
    const int b = n >> 11;
    const int op = op_t[b];
    const int pt = pt_t[n];
    const int j0 = tid * 4;

    float4 x  = *(const float4*)(g_h + (long)n * 1024 + j0);
    float4 ow = *(const float4*)(g_opw + op * 1024 + j0);
    float4 pw = *(const float4*)(g_ptw + pt * 1024 + j0);
    float4 cb = *(const float4*)(ctx_b + j0);
    float v0 = x.x + ow.x + pw.x + cb.x;
    float v1 = x.y + ow.y + pw.y + cb.y;
    float v2 = x.z + ow.z + pw.z + cb.z;
    float v3 = x.w + ow.w + pw.w + cb.w;

    float s = wred(v0 + v1 + v2 + v3);
    if (lane == 0) red[warp] = s;
    __syncthreads();
    float tot = 0.f;
#pragma unroll
    for (int w = 0; w < 8; w++) tot += red[w];
    const float mean = tot * (1.0f / 1024.0f);
    __syncthreads();

    float d0 = v0 - mean, d1 = v1 - mean, d2 = v2 - mean, d3 = v3 - mean;
    float ss = wred(d0 * d0 + d1 * d1 + d2 * d2 + d3 * d3);
    if (lane == 0) red[warp] = ss;
    __syncthreads();
    float tot2 = 0.f;
#pragma unroll
    for (int w = 0; w < 8; w++) tot2 += red[w];
    const float rs = rsqrtf(tot2 * (1.0f / 1024.0f) + 1e-5f);

    float4 gg = *(const float4*)(ctx_g + j0);
    float4 bb = *(const float4*)(ctx_beta + j0);
    float4 o;
    o.x = gelu_exact(d0 * rs * gg.x + bb.x);
    o.y = gelu_exact(d1 * rs * gg.y + bb.y);
    o.z = gelu_exact(d2 * rs * gg.z + bb.z);
    o.w = gelu_exact(d3 * rs * gg.w + bb.w);
    *(float4*)(g_ctx + (long)n * 1024 + j0) = o;
}

// ---------------------------------------------------------------------------
// Heads epilogue: block per token (256 thr), warp w = head w.
// bias -> LN(512)/GELU (aux: GELU only) -> GEMV(512 -> no) -> d_out.
// ---------------------------------------------------------------------------
__global__ __launch_bounds__(256) void heads_kernel(const float* __restrict__ sign_b1,
                                                    const float* __restrict__ sign_g,
                                                    const float* __restrict__ sign_beta,
                                                    const float* __restrict__ sign_w2,
                                                    const float* __restrict__ sign_b2,
                                                    const float* __restrict__ dig_g,
                                                    const float* __restrict__ dig_beta,
                                                    const float* __restrict__ dig_w2,
                                                    const float* __restrict__ dig_b2,
                                                    const float* __restrict__ aux_b1,
                                                    const float* __restrict__ aux_w2,
                                                    const float* __restrict__ aux_b2,
                                                    float* __restrict__ out) {
    const int n = blockIdx.x;
    const int tid = threadIdx.x;
    const int h = tid >> 5, lane = tid & 31;
    const int cbase = lane * 16;

    const float* hr = g_h + (long)n * 4096 + h * 512 + cbase;
    float v[16];
#pragma unroll
    for (int i = 0; i < 4; i++) {
        float4 t = *(const float4*)(hr + i * 4);
        v[4 * i + 0] = t.x; v[4 * i + 1] = t.y; v[4 * i + 2] = t.z; v[4 * i + 3] = t.w;
    }

    // bias
    if (h == 0) {
#pragma unroll
        for (int i = 0; i < 16; i++) v[i] += sign_b1[cbase + i];
    } else if (h < 7) {
#pragma unroll
        for (int i = 0; i < 16; i++) v[i] += g_posh[(h - 1) * 512 + cbase + i];
    } else {
#pragma unroll
        for (int i = 0; i < 16; i++) v[i] += aux_b1[cbase + i];
    }

    if (h < 7) {
        float s = 0.f;
#pragma unroll
        for (int i = 0; i < 16; i++) s += v[i];
        s = wred(s);
        const float mean = s * (1.0f / 512.0f);
        float ss = 0.f;
#pragma unroll
        for (int i = 0; i < 16; i++) { float d = v[i] - mean; ss += d * d; }
        ss = wred(ss);
        const float rs = rsqrtf(ss * (1.0f / 512.0f) + 1e-5f);
        const float* gg = (h == 0) ? sign_g    : dig_g    + (h - 1) * 512;
        const float* bb = (h == 0) ? sign_beta : dig_beta + (h - 1) * 512;
#pragma unroll
        for (int i = 0; i < 16; i++)
            v[i] = (v[i] - mean) * rs * gg[cbase + i] + bb[cbase + i];
    }
#pragma unroll
    for (int i = 0; i < 16; i++) v[i] = gelu_exact(v[i]);

    const int no = (h == 0) ? 3 : ((h == 7) ? 1 : 10);
    const float* W2 = (h == 0) ? sign_w2 : ((h == 7) ? aux_w2 : dig_w2 + (h - 1) * 5120);

    float acc[10];
#pragma unroll
    for (int o = 0; o < 10; o++) acc[o] = 0.f;
#pragma unroll
    for (int i = 0; i < 16; i++) {
        const float* wr = W2 + (cbase + i) * no;
        const float vv = v[i];
#pragma unroll
        for (int o = 0; o < 10; o++)
            if (o < no) acc[o] += vv * __ldg(wr + o);
    }
#pragma unroll
    for (int o = 0; o < 10; o++)
        if (o < no) acc[o] = wred(acc[o]);

    if (lane == 0) {
        if (h == 0) {
#pragma unroll
            for (int o = 0; o < 3; o++)
                out[OUT_SIGN + (long)n * 3 + o] = acc[o] + sign_b2[o];
        } else if (h < 7) {
            const int p = h - 1;
#pragma unroll
            for (int o = 0; o < 10; o++)
                out[OUT_DIG + (long)n * 60 + p * 10 + o] = acc[o] + dig_b2[p * 10 + o];
        } else {
            out[OUT_AUX + n] = acc[0] + aux_b2[0];
        }
    }
}

// ---------------------------------------------------------------------------
// Launch
// ---------------------------------------------------------------------------
extern "C" void kernel_launch(void* const* d_in, const int* in_sizes, int n_in,
                              void* d_out, int out_size) {
    const float* hidden    = (const float*)d_in[0];
    const int*   op_t      = (const int*)  d_in[1];
    const int*   pt_t      = (const int*)  d_in[2];
    const float* op_embed  = (const float*)d_in[3];
    const float* pt_embed  = (const float*)d_in[4];
    const float* pos_embed = (const float*)d_in[5];
    const float* ctx_w     = (const float*)d_in[6];
    const float* ctx_b     = (const float*)d_in[7];
    const float* ctx_g     = (const float*)d_in[8];
    const float* ctx_beta  = (const float*)d_in[9];
    const float* sign_w1   = (const float*)d_in[10];
    const float* sign_b1   = (const float*)d_in[11];
    const float* sign_g    = (const float*)d_in[12];
    const float* sign_beta = (const float*)d_in[13];
    const float* sign_w2   = (const float*)d_in[14];
    const float* sign_b2   = (const float*)d_in[15];
    const float* dig_w1    = (const float*)d_in[16];
    const float* dig_b1    = (const float*)d_in[17];
    const float* dig_g     = (const float*)d_in[18];
    const float* dig_beta  = (const float*)d_in[19];
    const float* dig_w2    = (const float*)d_in[20];
    const float* dig_b2    = (const float*)d_in[21];
    const float* aux_w1    = (const float*)d_in[22];
    const float* aux_b1    = (const float*)d_in[23];
    const float* aux_w2    = (const float*)d_in[24];
    const float* aux_b2    = (const float*)d_in[25];
    float* out = (float*)d_out;

    prep_small<<<88, 256>>>(op_embed, pt_embed, pos_embed, ctx_w, dig_w1, dig_b1);
    pack_w1<<<16384, 256>>>(sign_w1, dig_w1, aux_w1);

    // GEMM1: [16384,1024] x [1024,1024] -> g_h (pre-LN)
    gemm1_kernel<<<dim3(8, 128), 256>>>(hidden, ctx_w);
    ln_ctx_kernel<<<NTOK, 256>>>(op_t, pt_t, ctx_b, ctx_g, ctx_beta);

    // GEMM2: [16384,1024] x [1024,4096] -> g_h
    gemm2_kernel<<<dim3(32, 128), 256>>>();

    heads_kernel<<<NTOK, 256>>>(sign_b1, sign_g, sign_beta, sign_w2, sign_b2,
                                dig_g, dig_beta, dig_w2, dig_b2,
                                aux_b1, aux_w2, aux_b2, out);
}